// round 15
// baseline (speedup 1.0000x reference)
#include <cuda_runtime.h>
#include <cuda_bf16.h>
#include <stdint.h>
#include <math.h>

#define B_ROWS 16384
#define N_G    8192
#define D      256
#define MT     112                  // rows per CTA (146 full + 1 tail tile)
#define NBLK   147
#define NTile  128
#define NTILES (N_G / NTile)        // 64
#define NCHUNK (NTILES * 2)         // 128 chunks of K=128
#define NTHREADS 896                // 28 warps = 7 per SMSP exactly

#define STRA   264                  // halves per A row (256 + 8 pad)
#define STRB   136                  // halves per B row (128 + 8 pad)

#define SM_A_BYTES (MT * STRA * 2)              // 59136
#define B_STAGE    (NTile * STRB * 2)           // 34816
#define SM_BS      SM_A_BYTES
#define SM_TOP     (SM_BS + 3 * B_STAGE)        // 163584
#define SM_WIN     (SM_TOP + 7168)
#define SMEM_TOTAL (SM_WIN + 512)               // 171264

#define REPAIR_T   1e-1f

// ---------------- device scratch ----------------
__device__ __nv_bfloat16 d_gb[N_G * D];     // normalized g, bf16
__device__ __align__(16) float d_rnorm[N_G];
__device__ float         d_sums[N_G * D];
__device__ unsigned int  d_counts[N_G];

// ---------------- helpers ----------------
__device__ __forceinline__ uint32_t smem_u32(const void* p) {
    uint32_t a;
    asm("{ .reg .u64 t; cvta.to.shared.u64 t, %1; cvt.u32.u64 %0, t; }" : "=r"(a) : "l"(p));
    return a;
}
__device__ __forceinline__ uint32_t pack_bf2(float lo, float hi) {
    uint32_t r;
    asm("cvt.rn.bf16x2.f32 %0, %1, %2;" : "=r"(r) : "f"(hi), "f"(lo));
    return r;
}
__device__ __forceinline__ void ldm_x4(uint32_t r[4], uint32_t addr) {
    asm volatile("ldmatrix.sync.aligned.m8n8.x4.shared.b16 {%0,%1,%2,%3}, [%4];"
                 : "=r"(r[0]), "=r"(r[1]), "=r"(r[2]), "=r"(r[3]) : "r"(addr));
}
__device__ __forceinline__ void mma_bf16(float c[4], const uint32_t a[4], const uint32_t b[2]) {
    asm volatile(
        "mma.sync.aligned.m16n8k16.row.col.f32.bf16.bf16.f32 "
        "{%0,%1,%2,%3}, {%4,%5,%6,%7}, {%8,%9}, {%0,%1,%2,%3};"
        : "+f"(c[0]), "+f"(c[1]), "+f"(c[2]), "+f"(c[3])
        : "r"(a[0]), "r"(a[1]), "r"(a[2]), "r"(a[3]), "r"(b[0]), "r"(b[1]));
}
__device__ __forceinline__ void top2_merge(float& b1, int& i1, float& s1, int& j1,
                                           float b2, int i2, float s2, int j2) {
    if (b2 > b1 || (b2 == b1 && i2 < i1)) {
        float cs; int cj;
        if (b1 > s2 || (b1 == s2 && i1 < j2)) { cs = b1; cj = i1; } else { cs = s2; cj = j2; }
        b1 = b2; i1 = i2; s1 = cs; j1 = cj;
    } else if (b2 > s1 || (b2 == s1 && i2 < j1)) {
        s1 = b2; j1 = i2;
    }
}

// ---------------------------------------------------------------------------
// prep_g: warp-per-group. 1024 blocks x 256 thr (8 warps = 8 groups/block).
//   float4 loads, warp-only reduction, bf16x2-packed uint4 stores,
//   vectorized zeroing of d_sums.
// ---------------------------------------------------------------------------
__global__ void __launch_bounds__(256) prep_g_kernel(const float* __restrict__ gf) {
    const int wid  = threadIdx.x >> 5;
    const int lane = threadIdx.x & 31;
    const int g    = blockIdx.x * 8 + wid;

    float4 v0 = *(const float4*)&gf[(size_t)g * D + lane * 4];
    float4 v1 = *(const float4*)&gf[(size_t)g * D + 128 + lane * 4];

    float s = v0.x * v0.x + v0.y * v0.y + v0.z * v0.z + v0.w * v0.w
            + v1.x * v1.x + v1.y * v1.y + v1.z * v1.z + v1.w * v1.w;
    #pragma unroll
    for (int o = 16; o; o >>= 1) s += __shfl_xor_sync(0xFFFFFFFFu, s, o);

    float rn = 1.0f / fmaxf(sqrtf(s), 1e-12f);
    if (lane == 0) {
        d_rnorm[g] = rn;
        d_counts[g] = 0u;
    }

    uint2 p0, p1;
    p0.x = pack_bf2(v0.x * rn, v0.y * rn);
    p0.y = pack_bf2(v0.z * rn, v0.w * rn);
    p1.x = pack_bf2(v1.x * rn, v1.y * rn);
    p1.y = pack_bf2(v1.z * rn, v1.w * rn);
    uint2* dst = (uint2*)&d_gb[(size_t)g * D];
    dst[lane]      = p0;
    dst[32 + lane] = p1;

    // zero d_sums for this group (256 floats = 32 lanes x 2 float4)
    float4 z = make_float4(0.f, 0.f, 0.f, 0.f);
    float4* sz = (float4*)&d_sums[(size_t)g * D];
    sz[lane]      = z;
    sz[32 + lane] = z;
}

// ---------------------------------------------------------------------------
// main: bf16 m16n8k16; 28 warps 7(M)x4(N), warp tile 16x32; 147 CTAs (1 wave)
// ---------------------------------------------------------------------------
__global__ void __launch_bounds__(NTHREADS, 1)
assign_kernel(const float* __restrict__ x, const float* __restrict__ gf) {
    extern __shared__ char smem[];
    char*  As    = smem;                          // [112][264] bf16
    char*  Bs    = smem + SM_BS;                  // [3][128][136] bf16
    float* tb_s  = (float*)(smem + SM_TOP);       // [112 rows][4 wn]
    float* ts_s  = tb_s + 448;
    int*   tbi_s = (int*)(ts_s + 448);
    int*   tsi_s = tbi_s + 448;
    int*   swin  = (int*)(smem + SM_WIN);

    const int tid  = threadIdx.x;
    const int lane = tid & 31;
    const int wid  = tid >> 5;
    const int wm   = wid >> 2;         // 0..6
    const int wn   = wid & 3;          // 0..3
    const int l4   = lane >> 2;
    const int lq   = lane & 3;
    const int g8   = lane >> 3;
    const int r8   = lane & 7;
    const int bm   = blockIdx.x * MT;

    // ---- build A in SMEM (fused fp32->bf16 convert); tail rows clamped ----
    for (int i = tid; i < MT * 64; i += NTHREADS) {
        int m = i >> 6, q = i & 63;
        int row = bm + m;
        if (row > B_ROWS - 1) row = B_ROWS - 1;
        float4 v = *(const float4*)&x[(size_t)row * D + q * 4];
        uint2 p;
        p.x = pack_bf2(v.x, v.y);
        p.y = pack_bf2(v.z, v.w);
        *(uint2*)(As + m * (STRA * 2) + q * 8) = p;
    }

    // ---- ldmatrix row-base addresses ----
    const uint32_t aRow =
        smem_u32(As) + (wm * 16 + (g8 & 1) * 8 + r8) * (STRA * 2) + (g8 >> 1) * 16;
    uint32_t bRow[2];
    #pragma unroll
    for (int p = 0; p < 2; p++)
        bRow[p] = smem_u32(Bs) +
                  (wn * 32 + p * 16 + (g8 >> 1) * 8 + r8) * (STRB * 2) + (g8 & 1) * 16;

    // ---- B prefetch (threads 0..511): chunk t=(tile,kc), stage t%3 ----
    const int nrow = (tid & 511) >> 2;  // 0..127
    const int quar = tid & 3;           // 0..3
    auto prefetchB = [&](int t) {
        if (tid < 512) {
            int tile = t >> 1, kc = t & 1;
            const __nv_bfloat16* src =
                &d_gb[(size_t)(tile * NTile + nrow) * D + kc * 128 + quar * 32];
            uint32_t dst = smem_u32(Bs + (t % 3) * B_STAGE + nrow * (STRB * 2) + quar * 64);
            #pragma unroll
            for (int q = 0; q < 4; q++)
                asm volatile("cp.async.cg.shared.global [%0], [%1], 16;"
                             :: "r"(dst + q * 16), "l"(src + q * 8));
        }
    };

    prefetchB(0);
    asm volatile("cp.async.commit_group;");
    prefetchB(1);
    asm volatile("cp.async.commit_group;");

    float C[4][4];
    float tb[2], ts[2];
    int   tbi[2], tsi[2];
    #pragma unroll
    for (int h = 0; h < 2; h++) {
        tb[h] = -1e30f; ts[h] = -1e30f;
        tbi[h] = 0;     tsi[h] = 1;
    }

    for (int t = 0; t < NCHUNK; ++t) {
        const int tile = t >> 1, kc = t & 1;

        asm volatile("cp.async.wait_group 1;");
        __syncthreads();      // stage t ready; all warps done with stage (t-1)

        if (kc == 0) {
            #pragma unroll
            for (int nt = 0; nt < 4; nt++)
                #pragma unroll
                for (int r = 0; r < 4; r++) C[nt][r] = 0.0f;
        }

        const uint32_t stoff = (t % 3) * B_STAGE;
        const uint32_t akoff = kc * 256;

        #pragma unroll
        for (int s = 0; s < 8; s++) {
            uint32_t a[4];
            ldm_x4(a, aRow + akoff + s * 32);
            uint32_t b[2][4];
            ldm_x4(b[0], bRow[0] + stoff + s * 32);
            ldm_x4(b[1], bRow[1] + stoff + s * 32);
            #pragma unroll
            for (int p = 0; p < 2; p++) {
                mma_bf16(C[2 * p],     a, &b[p][0]);
                mma_bf16(C[2 * p + 1], a, &b[p][2]);
            }
        }

        if (t + 2 < NCHUNK) prefetchB(t + 2);
        asm volatile("cp.async.commit_group;");

        if (kc == 1) {
            const int bn = tile * NTile;
            #pragma unroll
            for (int nt = 0; nt < 4; nt++) {
                const int n0 = bn + wn * 32 + nt * 8 + 2 * lq;
                #pragma unroll
                for (int h = 0; h < 2; h++) {
                    float v0 = C[nt][2 * h];
                    float v1 = C[nt][2 * h + 1];
                    if (v0 > tb[h]) { ts[h] = tb[h]; tsi[h] = tbi[h]; tb[h] = v0; tbi[h] = n0; }
                    else if (v0 > ts[h]) { ts[h] = v0; tsi[h] = n0; }
                    if (v1 > tb[h]) { ts[h] = tb[h]; tsi[h] = tbi[h]; tb[h] = v1; tbi[h] = n0 + 1; }
                    else if (v1 > ts[h]) { ts[h] = v1; tsi[h] = n0 + 1; }
                }
            }
        }
    }

    // ---- cross-lane top-2 reduction within quads ----
    #pragma unroll
    for (int h = 0; h < 2; h++) {
        float b = tb[h], s = ts[h];
        int   bi = tbi[h], si = tsi[h];
        #pragma unroll
        for (int off = 1; off <= 2; off <<= 1) {
            float ob  = __shfl_xor_sync(0xFFFFFFFFu, b, off);
            float os  = __shfl_xor_sync(0xFFFFFFFFu, s, off);
            int   obi = __shfl_xor_sync(0xFFFFFFFFu, bi, off);
            int   osi = __shfl_xor_sync(0xFFFFFFFFu, si, off);
            top2_merge(b, bi, s, si, ob, obi, os, osi);
        }
        if (lq == 0) {
            int row = wm * 16 + h * 8 + l4;     // 0..111
            int idx = row * 4 + wn;
            tb_s[idx] = b; ts_s[idx] = s; tbi_s[idx] = bi; tsi_s[idx] = si;
        }
    }
    __syncthreads();

    // ---- per-row merge (4 wn partials) + exact fp32 repair + winner ----
    if (tid < MT && bm + tid < B_ROWS) {
        float b = tb_s[tid * 4], s = ts_s[tid * 4];
        int   bi = tbi_s[tid * 4], si = tsi_s[tid * 4];
        #pragma unroll
        for (int q = 1; q < 4; q++)
            top2_merge(b, bi, s, si, tb_s[tid * 4 + q], tbi_s[tid * 4 + q],
                       ts_s[tid * 4 + q], tsi_s[tid * 4 + q]);

        if (b - s < REPAIR_T) {
            const float* xr = x  + (size_t)(bm + tid) * D;
            const float* ga = gf + (size_t)bi * D;
            const float* gb = gf + (size_t)si * D;
            float va = 0.0f, vb = 0.0f;
            #pragma unroll 8
            for (int k = 0; k < D; k++) {
                float xv = xr[k];
                va = fmaf(xv, ga[k], va);
                vb = fmaf(xv, gb[k], vb);
            }
            va *= d_rnorm[bi];
            vb *= d_rnorm[si];
            if (vb > va || (vb == va && si < bi)) bi = si;
        }
        swin[tid] = bi;
        atomicAdd(&d_counts[bi], 1u);
    }
    __syncthreads();

    // ---- segment-sum scatter: threads 0..511 = 2 row-halves x 256 dims ----
    if (tid < 512) {
        int halfsel = tid >> 8;           // 0 or 1
        int dim     = tid & 255;
        int r0 = halfsel * 56, r1 = r0 + 56;
        for (int r = r0; r < r1; r++) {
            if (bm + r >= B_ROWS) break;
            int g = swin[r];
            atomicAdd(&d_sums[(size_t)g * D + dim], x[(size_t)(bm + r) * D + dim]);
        }
    }
}

// ---------------------------------------------------------------------------
// finalize (2x float4 per thread): out = 0.99*g + 0.01 * sums / max(count,1)
// ---------------------------------------------------------------------------
__global__ void __launch_bounds__(256) finalize_kernel(const float* __restrict__ gf,
                                                       float* __restrict__ out) {
    int i8 = blockIdx.x * 256 + threadIdx.x;
    int base = i8 * 8;
    int g = base >> 8;
    unsigned int c = d_counts[g];
    float rc = 0.01f / (float)(c > 1u ? c : 1u);
    #pragma unroll
    for (int q = 0; q < 2; q++) {
        int b = base + q * 4;
        float4 gv = *(const float4*)&gf[b];
        float4 sv = *(const float4*)&d_sums[b];
        float4 o;
        o.x = 0.99f * gv.x + sv.x * rc;
        o.y = 0.99f * gv.y + sv.y * rc;
        o.z = 0.99f * gv.z + sv.z * rc;
        o.w = 0.99f * gv.w + sv.w * rc;
        *(float4*)&out[b] = o;
    }
}

// ---------------------------------------------------------------------------
extern "C" void kernel_launch(void* const* d_in, const int* in_sizes, int n_in,
                              void* d_out, int out_size) {
    const float* x;
    const float* gf;
    if (in_sizes[0] == B_ROWS * D) {
        x  = (const float*)d_in[0];
        gf = (const float*)d_in[1];
    } else {
        x  = (const float*)d_in[1];
        gf = (const float*)d_in[0];
    }
    float* out = (float*)d_out;

    cudaFuncSetAttribute(assign_kernel, cudaFuncAttributeMaxDynamicSharedMemorySize, SMEM_TOTAL);

    prep_g_kernel<<<N_G / 8, 256>>>(gf);
    assign_kernel<<<NBLK, NTHREADS, SMEM_TOTAL>>>(x, gf);
    finalize_kernel<<<(N_G * D / 8) / 256, 256>>>(gf, out);
}

// round 16
// speedup vs baseline: 1.5407x; 1.5407x over previous
#include <cuda_runtime.h>
#include <cuda_bf16.h>
#include <stdint.h>
#include <math.h>

#define B_ROWS 16384
#define N_G    8192
#define D      256
#define MT     112                  // rows per CTA (146 full + 1 tail + 1 dummy)
#define NBLK   148                  // one CTA per SM, grid >= 148
#define NTile  128
#define NTILES (N_G / NTile)        // 64
#define NCHUNK (NTILES * 2)         // 128 chunks of K=128
#define NTHREADS 896                // 28 warps = 7 per SMSP exactly

#define STRA   264                  // halves per A row (256 + 8 pad)
#define STRB   136                  // halves per B row (128 + 8 pad)

#define SM_A_BYTES (MT * STRA * 2)              // 59136
#define B_STAGE    (NTile * STRB * 2)           // 34816
#define SM_BS      SM_A_BYTES
#define SM_TOP     (SM_BS + 3 * B_STAGE)        // 163584
#define SM_WIN     (SM_TOP + 7168)
#define SMEM_TOTAL (SM_WIN + 512)               // 171264

#define REPAIR_T   1e-1f

// ---------------- device scratch ----------------
__device__ __nv_bfloat16 d_gb[N_G * D];     // normalized g, bf16
__device__ float         d_rnorm[N_G];
__device__ float         d_sums[N_G * D];
__device__ unsigned int  d_counts[N_G];

// ---------------- helpers ----------------
__device__ __forceinline__ uint32_t smem_u32(const void* p) {
    uint32_t a;
    asm("{ .reg .u64 t; cvta.to.shared.u64 t, %1; cvt.u32.u64 %0, t; }" : "=r"(a) : "l"(p));
    return a;
}
__device__ __forceinline__ uint32_t pack_bf2(float lo, float hi) {
    uint32_t r;
    asm("cvt.rn.bf16x2.f32 %0, %1, %2;" : "=r"(r) : "f"(hi), "f"(lo));
    return r;
}
__device__ __forceinline__ void ldm_x4(uint32_t r[4], uint32_t addr) {
    asm volatile("ldmatrix.sync.aligned.m8n8.x4.shared.b16 {%0,%1,%2,%3}, [%4];"
                 : "=r"(r[0]), "=r"(r[1]), "=r"(r[2]), "=r"(r[3]) : "r"(addr));
}
__device__ __forceinline__ void mma_bf16(float c[4], const uint32_t a[4], const uint32_t b[2]) {
    asm volatile(
        "mma.sync.aligned.m16n8k16.row.col.f32.bf16.bf16.f32 "
        "{%0,%1,%2,%3}, {%4,%5,%6,%7}, {%8,%9}, {%0,%1,%2,%3};"
        : "+f"(c[0]), "+f"(c[1]), "+f"(c[2]), "+f"(c[3])
        : "r"(a[0]), "r"(a[1]), "r"(a[2]), "r"(a[3]), "r"(b[0]), "r"(b[1]));
}
__device__ __forceinline__ void top2_merge(float& b1, int& i1, float& s1, int& j1,
                                           float b2, int i2, float s2, int j2) {
    if (b2 > b1 || (b2 == b1 && i2 < i1)) {
        float cs; int cj;
        if (b1 > s2 || (b1 == s2 && i1 < j2)) { cs = b1; cj = i1; } else { cs = s2; cj = j2; }
        b1 = b2; i1 = i2; s1 = cs; j1 = cj;
    } else if (b2 > s1 || (b2 == s1 && i2 < j1)) {
        s1 = b2; j1 = i2;
    }
}

// ---------------------------------------------------------------------------
// prep: normalize g -> bf16; zero sums/counts; keep rnorm  (R14-proven form)
// ---------------------------------------------------------------------------
__global__ void __launch_bounds__(256) prep_g_kernel(const float* __restrict__ gf) {
    int g = blockIdx.x;
    int t = threadIdx.x;
    float v = gf[g * D + t];
    d_sums[g * D + t] = 0.0f;

    float s = v * v;
    #pragma unroll
    for (int o = 16; o; o >>= 1) s += __shfl_xor_sync(0xFFFFFFFFu, s, o);
    __shared__ float red[8];
    __shared__ float srn;
    if ((t & 31) == 0) red[t >> 5] = s;
    __syncthreads();
    if (t < 8) {
        float r = red[t];
        #pragma unroll
        for (int o = 4; o; o >>= 1) r += __shfl_xor_sync(0xFFu, r, o);
        if (t == 0) {
            float rn = 1.0f / fmaxf(sqrtf(r), 1e-12f);
            srn = rn;
            d_rnorm[g] = rn;
            d_counts[g] = 0u;
        }
    }
    __syncthreads();
    d_gb[g * D + t] = __float2bfloat16(v * srn);
}

// ---------------------------------------------------------------------------
// main: bf16 m16n8k16; 28 warps 7(M)x4(N), warp tile 16x32; 148 CTAs (1 wave)
// ---------------------------------------------------------------------------
__global__ void __launch_bounds__(NTHREADS, 1)
assign_kernel(const float* __restrict__ x, const float* __restrict__ gf) {
    extern __shared__ char smem[];
    char*  As    = smem;                          // [112][264] bf16
    char*  Bs    = smem + SM_BS;                  // [3][128][136] bf16
    float* tb_s  = (float*)(smem + SM_TOP);       // [112 rows][4 wn]
    float* ts_s  = tb_s + 448;
    int*   tbi_s = (int*)(ts_s + 448);
    int*   tsi_s = tbi_s + 448;
    int*   swin  = (int*)(smem + SM_WIN);

    const int tid  = threadIdx.x;
    const int lane = tid & 31;
    const int wid  = tid >> 5;
    const int wm   = wid >> 2;         // 0..6
    const int wn   = wid & 3;          // 0..3
    const int l4   = lane >> 2;
    const int lq   = lane & 3;
    const int g8   = lane >> 3;
    const int r8   = lane & 7;
    const int bm   = blockIdx.x * MT;

    // ---- build A in SMEM (fused fp32->bf16 convert); tail rows clamped ----
    for (int i = tid; i < MT * 64; i += NTHREADS) {
        int m = i >> 6, q = i & 63;
        int row = bm + m;
        if (row > B_ROWS - 1) row = B_ROWS - 1;
        float4 v = *(const float4*)&x[(size_t)row * D + q * 4];
        uint2 p;
        p.x = pack_bf2(v.x, v.y);
        p.y = pack_bf2(v.z, v.w);
        *(uint2*)(As + m * (STRA * 2) + q * 8) = p;
    }

    // ---- ldmatrix row-base addresses ----
    const uint32_t aRow =
        smem_u32(As) + (wm * 16 + (g8 & 1) * 8 + r8) * (STRA * 2) + (g8 >> 1) * 16;
    uint32_t bRow[2];
    #pragma unroll
    for (int p = 0; p < 2; p++)
        bRow[p] = smem_u32(Bs) +
                  (wn * 32 + p * 16 + (g8 >> 1) * 8 + r8) * (STRB * 2) + (g8 & 1) * 16;

    // ---- B prefetch (threads 0..511): chunk t=(tile,kc), stage t%3 ----
    const int nrow = (tid & 511) >> 2;  // 0..127
    const int quar = tid & 3;           // 0..3
    auto prefetchB = [&](int t) {
        if (tid < 512) {
            int tile = t >> 1, kc = t & 1;
            const __nv_bfloat16* src =
                &d_gb[(size_t)(tile * NTile + nrow) * D + kc * 128 + quar * 32];
            uint32_t dst = smem_u32(Bs + (t % 3) * B_STAGE + nrow * (STRB * 2) + quar * 64);
            #pragma unroll
            for (int q = 0; q < 4; q++)
                asm volatile("cp.async.cg.shared.global [%0], [%1], 16;"
                             :: "r"(dst + q * 16), "l"(src + q * 8));
        }
    };

    prefetchB(0);
    asm volatile("cp.async.commit_group;");
    prefetchB(1);
    asm volatile("cp.async.commit_group;");

    float C[4][4];
    float tb[2], ts[2];
    int   tbi[2], tsi[2];
    #pragma unroll
    for (int h = 0; h < 2; h++) {
        tb[h] = -1e30f; ts[h] = -1e30f;
        tbi[h] = 0;     tsi[h] = 1;
    }

    for (int t = 0; t < NCHUNK; ++t) {
        const int tile = t >> 1, kc = t & 1;

        asm volatile("cp.async.wait_group 1;");
        __syncthreads();      // stage t ready; all warps done with stage (t-1)

        if (kc == 0) {
            #pragma unroll
            for (int nt = 0; nt < 4; nt++)
                #pragma unroll
                for (int r = 0; r < 4; r++) C[nt][r] = 0.0f;
        }

        const uint32_t stoff = (t % 3) * B_STAGE;
        const uint32_t akoff = kc * 256;

        #pragma unroll
        for (int s = 0; s < 8; s++) {
            uint32_t a[4];
            ldm_x4(a, aRow + akoff + s * 32);
            uint32_t b[2][4];
            ldm_x4(b[0], bRow[0] + stoff + s * 32);
            ldm_x4(b[1], bRow[1] + stoff + s * 32);
            #pragma unroll
            for (int p = 0; p < 2; p++) {
                mma_bf16(C[2 * p],     a, &b[p][0]);
                mma_bf16(C[2 * p + 1], a, &b[p][2]);
            }
        }

        if (t + 2 < NCHUNK) prefetchB(t + 2);
        asm volatile("cp.async.commit_group;");

        if (kc == 1) {
            const int bn = tile * NTile;
            #pragma unroll
            for (int nt = 0; nt < 4; nt++) {
                const int n0 = bn + wn * 32 + nt * 8 + 2 * lq;
                #pragma unroll
                for (int h = 0; h < 2; h++) {
                    float v0 = C[nt][2 * h];
                    float v1 = C[nt][2 * h + 1];
                    if (v0 > tb[h]) { ts[h] = tb[h]; tsi[h] = tbi[h]; tb[h] = v0; tbi[h] = n0; }
                    else if (v0 > ts[h]) { ts[h] = v0; tsi[h] = n0; }
                    if (v1 > tb[h]) { ts[h] = tb[h]; tsi[h] = tbi[h]; tb[h] = v1; tbi[h] = n0 + 1; }
                    else if (v1 > ts[h]) { ts[h] = v1; tsi[h] = n0 + 1; }
                }
            }
        }
    }

    // ---- cross-lane top-2 reduction within quads ----
    #pragma unroll
    for (int h = 0; h < 2; h++) {
        float b = tb[h], s = ts[h];
        int   bi = tbi[h], si = tsi[h];
        #pragma unroll
        for (int off = 1; off <= 2; off <<= 1) {
            float ob  = __shfl_xor_sync(0xFFFFFFFFu, b, off);
            float os  = __shfl_xor_sync(0xFFFFFFFFu, s, off);
            int   obi = __shfl_xor_sync(0xFFFFFFFFu, bi, off);
            int   osi = __shfl_xor_sync(0xFFFFFFFFu, si, off);
            top2_merge(b, bi, s, si, ob, obi, os, osi);
        }
        if (lq == 0) {
            int row = wm * 16 + h * 8 + l4;     // 0..111
            int idx = row * 4 + wn;
            tb_s[idx] = b; ts_s[idx] = s; tbi_s[idx] = bi; tsi_s[idx] = si;
        }
    }
    __syncthreads();

    // ---- per-row merge (4 wn partials) + exact fp32 repair + winner ----
    if (tid < MT && bm + tid < B_ROWS) {
        float b = tb_s[tid * 4], s = ts_s[tid * 4];
        int   bi = tbi_s[tid * 4], si = tsi_s[tid * 4];
        #pragma unroll
        for (int q = 1; q < 4; q++)
            top2_merge(b, bi, s, si, tb_s[tid * 4 + q], tbi_s[tid * 4 + q],
                       ts_s[tid * 4 + q], tsi_s[tid * 4 + q]);

        if (b - s < REPAIR_T) {
            const float* xr = x  + (size_t)(bm + tid) * D;
            const float* ga = gf + (size_t)bi * D;
            const float* gb = gf + (size_t)si * D;
            float va = 0.0f, vb = 0.0f;
            #pragma unroll 8
            for (int k = 0; k < D; k++) {
                float xv = xr[k];
                va = fmaf(xv, ga[k], va);
                vb = fmaf(xv, gb[k], vb);
            }
            va *= d_rnorm[bi];
            vb *= d_rnorm[si];
            if (vb > va || (vb == va && si < bi)) bi = si;
        }
        swin[tid] = bi;
        atomicAdd(&d_counts[bi], 1u);
    }
    __syncthreads();

    // ---- segment-sum scatter: threads 0..511 = 2 row-halves x 256 dims ----
    if (tid < 512) {
        int halfsel = tid >> 8;           // 0 or 1
        int dim     = tid & 255;
        int r0 = halfsel * 56, r1 = r0 + 56;
        for (int r = r0; r < r1; r++) {
            if (bm + r >= B_ROWS) break;
            int g = swin[r];
            atomicAdd(&d_sums[(size_t)g * D + dim], x[(size_t)(bm + r) * D + dim]);
        }
    }
}

// ---------------------------------------------------------------------------
// finalize (float4): out = 0.99*g + 0.01 * sums / max(count,1)  (R14-proven)
// ---------------------------------------------------------------------------
__global__ void __launch_bounds__(256) finalize_kernel(const float* __restrict__ gf,
                                                       float* __restrict__ out) {
    int i4 = blockIdx.x * 256 + threadIdx.x;
    int base = i4 * 4;
    int g = base >> 8;
    unsigned int c = d_counts[g];
    float rc = 0.01f / (float)(c > 1u ? c : 1u);
    float4 gv = *(const float4*)&gf[base];
    float4 sv = *(const float4*)&d_sums[base];
    float4 o;
    o.x = 0.99f * gv.x + sv.x * rc;
    o.y = 0.99f * gv.y + sv.y * rc;
    o.z = 0.99f * gv.z + sv.z * rc;
    o.w = 0.99f * gv.w + sv.w * rc;
    *(float4*)&out[base] = o;
}

// ---------------------------------------------------------------------------
extern "C" void kernel_launch(void* const* d_in, const int* in_sizes, int n_in,
                              void* d_out, int out_size) {
    const float* x;
    const float* gf;
    if (in_sizes[0] == B_ROWS * D) {
        x  = (const float*)d_in[0];
        gf = (const float*)d_in[1];
    } else {
        x  = (const float*)d_in[1];
        gf = (const float*)d_in[0];
    }
    float* out = (float*)d_out;

    cudaFuncSetAttribute(assign_kernel, cudaFuncAttributeMaxDynamicSharedMemorySize, SMEM_TOTAL);

    prep_g_kernel<<<N_G, 256>>>(gf);
    assign_kernel<<<NBLK, NTHREADS, SMEM_TOTAL>>>(x, gf);
    finalize_kernel<<<(N_G * D / 4) / 256, 256>>>(gf, out);
}

// round 17
// speedup vs baseline: 1.5532x; 1.0081x over previous
#include <cuda_runtime.h>
#include <cuda_bf16.h>
#include <stdint.h>
#include <math.h>

#define B_ROWS 16384
#define N_G    8192
#define D      256
#define MT     112                  // rows per CTA (146 full + 1 tail + 1 dummy)
#define NBLK   148                  // one CTA per SM, grid >= 148
#define NTile  128
#define NTILES (N_G / NTile)        // 64
#define NCHUNK (NTILES * 2)         // 128 chunks of K=128
#define NTHREADS 896                // 28 warps = 7 per SMSP exactly

#define STRA   264                  // halves per A row (256 + 8 pad)
#define STRB   136                  // halves per B row (128 + 8 pad)

#define SM_A_BYTES (MT * STRA * 2)              // 59136
#define B_STAGE    (NTile * STRB * 2)           // 34816
#define SM_BS      SM_A_BYTES
#define SM_TOP     (SM_BS + 3 * B_STAGE)        // 163584
#define SM_WIN     (SM_TOP + 7168)
#define SMEM_TOTAL (SM_WIN + 512)               // 171264

#define REPAIR_T   1e-1f

// ---------------- device scratch ----------------
__device__ __nv_bfloat16 d_gb[N_G * D];     // normalized g, bf16
__device__ __align__(16) float d_rnorm[N_G];
__device__ float         d_sums[N_G * D];
__device__ unsigned int  d_counts[N_G];

// ---------------- helpers ----------------
__device__ __forceinline__ uint32_t smem_u32(const void* p) {
    uint32_t a;
    asm("{ .reg .u64 t; cvta.to.shared.u64 t, %1; cvt.u32.u64 %0, t; }" : "=r"(a) : "l"(p));
    return a;
}
__device__ __forceinline__ uint32_t pack_bf2(float lo, float hi) {
    uint32_t r;
    asm("cvt.rn.bf16x2.f32 %0, %1, %2;" : "=r"(r) : "f"(hi), "f"(lo));
    return r;
}
__device__ __forceinline__ void ldm_x4(uint32_t r[4], uint32_t addr) {
    asm volatile("ldmatrix.sync.aligned.m8n8.x4.shared.b16 {%0,%1,%2,%3}, [%4];"
                 : "=r"(r[0]), "=r"(r[1]), "=r"(r[2]), "=r"(r[3]) : "r"(addr));
}
__device__ __forceinline__ void mma_bf16(float c[4], const uint32_t a[4], const uint32_t b[2]) {
    asm volatile(
        "mma.sync.aligned.m16n8k16.row.col.f32.bf16.bf16.f32 "
        "{%0,%1,%2,%3}, {%4,%5,%6,%7}, {%8,%9}, {%0,%1,%2,%3};"
        : "+f"(c[0]), "+f"(c[1]), "+f"(c[2]), "+f"(c[3])
        : "r"(a[0]), "r"(a[1]), "r"(a[2]), "r"(a[3]), "r"(b[0]), "r"(b[1]));
}
__device__ __forceinline__ void top2_merge(float& b1, int& i1, float& s1, int& j1,
                                           float b2, int i2, float s2, int j2) {
    if (b2 > b1 || (b2 == b1 && i2 < i1)) {
        float cs; int cj;
        if (b1 > s2 || (b1 == s2 && i1 < j2)) { cs = b1; cj = i1; } else { cs = s2; cj = j2; }
        b1 = b2; i1 = i2; s1 = cs; j1 = cj;
    } else if (b2 > s1 || (b2 == s1 && i2 < j1)) {
        s1 = b2; j1 = i2;
    }
}

// ---------------------------------------------------------------------------
// prep_g: warp-per-group (R15-measured: 8.6us, correct). 1024 blocks x 256.
// ---------------------------------------------------------------------------
__global__ void __launch_bounds__(256) prep_g_kernel(const float* __restrict__ gf) {
    const int wid  = threadIdx.x >> 5;
    const int lane = threadIdx.x & 31;
    const int g    = blockIdx.x * 8 + wid;

    float4 v0 = *(const float4*)&gf[(size_t)g * D + lane * 4];
    float4 v1 = *(const float4*)&gf[(size_t)g * D + 128 + lane * 4];

    float s = v0.x * v0.x + v0.y * v0.y + v0.z * v0.z + v0.w * v0.w
            + v1.x * v1.x + v1.y * v1.y + v1.z * v1.z + v1.w * v1.w;
    #pragma unroll
    for (int o = 16; o; o >>= 1) s += __shfl_xor_sync(0xFFFFFFFFu, s, o);

    float rn = 1.0f / fmaxf(sqrtf(s), 1e-12f);
    if (lane == 0) {
        d_rnorm[g] = rn;
        d_counts[g] = 0u;
    }

    uint2 p0, p1;
    p0.x = pack_bf2(v0.x * rn, v0.y * rn);
    p0.y = pack_bf2(v0.z * rn, v0.w * rn);
    p1.x = pack_bf2(v1.x * rn, v1.y * rn);
    p1.y = pack_bf2(v1.z * rn, v1.w * rn);
    uint2* dst = (uint2*)&d_gb[(size_t)g * D];
    dst[lane]      = p0;
    dst[32 + lane] = p1;

    float4 z = make_float4(0.f, 0.f, 0.f, 0.f);
    float4* sz = (float4*)&d_sums[(size_t)g * D];
    sz[lane]      = z;
    sz[32 + lane] = z;
}

// ---------------------------------------------------------------------------
// main: bf16 m16n8k16; 28 warps 7(M)x4(N), warp tile 16x32; 148 CTAs (1 wave)
//   (byte-identical to R16 assign)
// ---------------------------------------------------------------------------
__global__ void __launch_bounds__(NTHREADS, 1)
assign_kernel(const float* __restrict__ x, const float* __restrict__ gf) {
    extern __shared__ char smem[];
    char*  As    = smem;                          // [112][264] bf16
    char*  Bs    = smem + SM_BS;                  // [3][128][136] bf16
    float* tb_s  = (float*)(smem + SM_TOP);       // [112 rows][4 wn]
    float* ts_s  = tb_s + 448;
    int*   tbi_s = (int*)(ts_s + 448);
    int*   tsi_s = tbi_s + 448;
    int*   swin  = (int*)(smem + SM_WIN);

    const int tid  = threadIdx.x;
    const int lane = tid & 31;
    const int wid  = tid >> 5;
    const int wm   = wid >> 2;         // 0..6
    const int wn   = wid & 3;          // 0..3
    const int l4   = lane >> 2;
    const int lq   = lane & 3;
    const int g8   = lane >> 3;
    const int r8   = lane & 7;
    const int bm   = blockIdx.x * MT;

    // ---- build A in SMEM (fused fp32->bf16 convert); tail rows clamped ----
    for (int i = tid; i < MT * 64; i += NTHREADS) {
        int m = i >> 6, q = i & 63;
        int row = bm + m;
        if (row > B_ROWS - 1) row = B_ROWS - 1;
        float4 v = *(const float4*)&x[(size_t)row * D + q * 4];
        uint2 p;
        p.x = pack_bf2(v.x, v.y);
        p.y = pack_bf2(v.z, v.w);
        *(uint2*)(As + m * (STRA * 2) + q * 8) = p;
    }

    // ---- ldmatrix row-base addresses ----
    const uint32_t aRow =
        smem_u32(As) + (wm * 16 + (g8 & 1) * 8 + r8) * (STRA * 2) + (g8 >> 1) * 16;
    uint32_t bRow[2];
    #pragma unroll
    for (int p = 0; p < 2; p++)
        bRow[p] = smem_u32(Bs) +
                  (wn * 32 + p * 16 + (g8 >> 1) * 8 + r8) * (STRB * 2) + (g8 & 1) * 16;

    // ---- B prefetch (threads 0..511): chunk t=(tile,kc), stage t%3 ----
    const int nrow = (tid & 511) >> 2;  // 0..127
    const int quar = tid & 3;           // 0..3
    auto prefetchB = [&](int t) {
        if (tid < 512) {
            int tile = t >> 1, kc = t & 1;
            const __nv_bfloat16* src =
                &d_gb[(size_t)(tile * NTile + nrow) * D + kc * 128 + quar * 32];
            uint32_t dst = smem_u32(Bs + (t % 3) * B_STAGE + nrow * (STRB * 2) + quar * 64);
            #pragma unroll
            for (int q = 0; q < 4; q++)
                asm volatile("cp.async.cg.shared.global [%0], [%1], 16;"
                             :: "r"(dst + q * 16), "l"(src + q * 8));
        }
    };

    prefetchB(0);
    asm volatile("cp.async.commit_group;");
    prefetchB(1);
    asm volatile("cp.async.commit_group;");

    float C[4][4];
    float tb[2], ts[2];
    int   tbi[2], tsi[2];
    #pragma unroll
    for (int h = 0; h < 2; h++) {
        tb[h] = -1e30f; ts[h] = -1e30f;
        tbi[h] = 0;     tsi[h] = 1;
    }

    for (int t = 0; t < NCHUNK; ++t) {
        const int tile = t >> 1, kc = t & 1;

        asm volatile("cp.async.wait_group 1;");
        __syncthreads();      // stage t ready; all warps done with stage (t-1)

        if (kc == 0) {
            #pragma unroll
            for (int nt = 0; nt < 4; nt++)
                #pragma unroll
                for (int r = 0; r < 4; r++) C[nt][r] = 0.0f;
        }

        const uint32_t stoff = (t % 3) * B_STAGE;
        const uint32_t akoff = kc * 256;

        #pragma unroll
        for (int s = 0; s < 8; s++) {
            uint32_t a[4];
            ldm_x4(a, aRow + akoff + s * 32);
            uint32_t b[2][4];
            ldm_x4(b[0], bRow[0] + stoff + s * 32);
            ldm_x4(b[1], bRow[1] + stoff + s * 32);
            #pragma unroll
            for (int p = 0; p < 2; p++) {
                mma_bf16(C[2 * p],     a, &b[p][0]);
                mma_bf16(C[2 * p + 1], a, &b[p][2]);
            }
        }

        if (t + 2 < NCHUNK) prefetchB(t + 2);
        asm volatile("cp.async.commit_group;");

        if (kc == 1) {
            const int bn = tile * NTile;
            #pragma unroll
            for (int nt = 0; nt < 4; nt++) {
                const int n0 = bn + wn * 32 + nt * 8 + 2 * lq;
                #pragma unroll
                for (int h = 0; h < 2; h++) {
                    float v0 = C[nt][2 * h];
                    float v1 = C[nt][2 * h + 1];
                    if (v0 > tb[h]) { ts[h] = tb[h]; tsi[h] = tbi[h]; tb[h] = v0; tbi[h] = n0; }
                    else if (v0 > ts[h]) { ts[h] = v0; tsi[h] = n0; }
                    if (v1 > tb[h]) { ts[h] = tb[h]; tsi[h] = tbi[h]; tb[h] = v1; tbi[h] = n0 + 1; }
                    else if (v1 > ts[h]) { ts[h] = v1; tsi[h] = n0 + 1; }
                }
            }
        }
    }

    // ---- cross-lane top-2 reduction within quads ----
    #pragma unroll
    for (int h = 0; h < 2; h++) {
        float b = tb[h], s = ts[h];
        int   bi = tbi[h], si = tsi[h];
        #pragma unroll
        for (int off = 1; off <= 2; off <<= 1) {
            float ob  = __shfl_xor_sync(0xFFFFFFFFu, b, off);
            float os  = __shfl_xor_sync(0xFFFFFFFFu, s, off);
            int   obi = __shfl_xor_sync(0xFFFFFFFFu, bi, off);
            int   osi = __shfl_xor_sync(0xFFFFFFFFu, si, off);
            top2_merge(b, bi, s, si, ob, obi, os, osi);
        }
        if (lq == 0) {
            int row = wm * 16 + h * 8 + l4;     // 0..111
            int idx = row * 4 + wn;
            tb_s[idx] = b; ts_s[idx] = s; tbi_s[idx] = bi; tsi_s[idx] = si;
        }
    }
    __syncthreads();

    // ---- per-row merge (4 wn partials) + exact fp32 repair + winner ----
    if (tid < MT && bm + tid < B_ROWS) {
        float b = tb_s[tid * 4], s = ts_s[tid * 4];
        int   bi = tbi_s[tid * 4], si = tsi_s[tid * 4];
        #pragma unroll
        for (int q = 1; q < 4; q++)
            top2_merge(b, bi, s, si, tb_s[tid * 4 + q], tbi_s[tid * 4 + q],
                       ts_s[tid * 4 + q], tsi_s[tid * 4 + q]);

        if (b - s < REPAIR_T) {
            const float* xr = x  + (size_t)(bm + tid) * D;
            const float* ga = gf + (size_t)bi * D;
            const float* gb = gf + (size_t)si * D;
            float va = 0.0f, vb = 0.0f;
            #pragma unroll 8
            for (int k = 0; k < D; k++) {
                float xv = xr[k];
                va = fmaf(xv, ga[k], va);
                vb = fmaf(xv, gb[k], vb);
            }
            va *= d_rnorm[bi];
            vb *= d_rnorm[si];
            if (vb > va || (vb == va && si < bi)) bi = si;
        }
        swin[tid] = bi;
        atomicAdd(&d_counts[bi], 1u);
    }
    __syncthreads();

    // ---- segment-sum scatter: threads 0..511 = 2 row-halves x 256 dims ----
    if (tid < 512) {
        int halfsel = tid >> 8;           // 0 or 1
        int dim     = tid & 255;
        int r0 = halfsel * 56, r1 = r0 + 56;
        for (int r = r0; r < r1; r++) {
            if (bm + r >= B_ROWS) break;
            int g = swin[r];
            atomicAdd(&d_sums[(size_t)g * D + dim], x[(size_t)(bm + r) * D + dim]);
        }
    }
}

// ---------------------------------------------------------------------------
// finalize (2x float4 per thread): out = 0.99*g + 0.01 * sums / max(count,1)
// ---------------------------------------------------------------------------
__global__ void __launch_bounds__(256) finalize_kernel(const float* __restrict__ gf,
                                                       float* __restrict__ out) {
    int i8 = blockIdx.x * 256 + threadIdx.x;
    int base = i8 * 8;
    int g = base >> 8;
    unsigned int c = d_counts[g];
    float rc = 0.01f / (float)(c > 1u ? c : 1u);
    #pragma unroll
    for (int q = 0; q < 2; q++) {
        int b = base + q * 4;
        float4 gv = *(const float4*)&gf[b];
        float4 sv = *(const float4*)&d_sums[b];
        float4 o;
        o.x = 0.99f * gv.x + sv.x * rc;
        o.y = 0.99f * gv.y + sv.y * rc;
        o.z = 0.99f * gv.z + sv.z * rc;
        o.w = 0.99f * gv.w + sv.w * rc;
        *(float4*)&out[b] = o;
    }
}

// ---------------------------------------------------------------------------
extern "C" void kernel_launch(void* const* d_in, const int* in_sizes, int n_in,
                              void* d_out, int out_size) {
    const float* x;
    const float* gf;
    if (in_sizes[0] == B_ROWS * D) {
        x  = (const float*)d_in[0];
        gf = (const float*)d_in[1];
    } else {
        x  = (const float*)d_in[1];
        gf = (const float*)d_in[0];
    }
    float* out = (float*)d_out;

    cudaFuncSetAttribute(assign_kernel, cudaFuncAttributeMaxDynamicSharedMemorySize, SMEM_TOTAL);

    prep_g_kernel<<<N_G / 8, 256>>>(gf);
    assign_kernel<<<NBLK, NTHREADS, SMEM_TOTAL>>>(x, gf);
    finalize_kernel<<<(N_G * D / 8) / 256, 256>>>(gf, out);
}